// round 10
// baseline (speedup 1.0000x reference)
#include <cuda_runtime.h>
#include <cstdint>

typedef unsigned long long ull;

#define SEQ    512
#define BATCH  128
#define INPUT  128
#define HIDDEN 512
#define CLUSTER 8
#define THREADS 512

// ---- recurrent smem layout (bytes) ----
// W slice  [512 k][64 n] fp32                       131072
// hc: [e4][par2][512 k][b2] fp32 (4096 per e,par)    32768
// stg: [e4][par2][128] fp32 (512 per e,par)           4096
// scr: [e4][kq16][b2][n64] fp32 (8192 per e)         32768
// mbar: [e4][par2] x 8B                                 64
#define HC_OFF   131072
#define STG_OFF  163840
#define SCR_OFF  167936
#define MB_OFF   200704
#define SMEM_BYTES 200832
#define EXCH_BYTES 4096u     // per engine-step: 8 ranks x 512B

// ---------------------------------------------------------------------------
// Phase 1: proj[row,n] = sum_k input[row,k] * W_in[n,k] -> d_out
// ---------------------------------------------------------------------------
__global__ __launch_bounds__(256) void proj_kernel(
    const float* __restrict__ A, const float* __restrict__ W,
    float* __restrict__ C)
{
    __shared__ float As[64][65];
    __shared__ float Bs[64][65];
    const int tid = threadIdx.x, tx = tid & 15, ty = tid >> 4;
    const int row0 = blockIdx.x * 64, n0 = blockIdx.y * 64;
    float acc[4][4] = {};
    for (int k0 = 0; k0 < INPUT; k0 += 64) {
        #pragma unroll
        for (int i = 0; i < 16; i++) {
            int e = tid + i * 256, r = e >> 6, kk = e & 63;
            As[kk][r] = A[(row0 + r) * INPUT + k0 + kk];
            Bs[kk][r] = W[(n0 + r) * INPUT + k0 + kk];
        }
        __syncthreads();
        #pragma unroll 8
        for (int k = 0; k < 64; k++) {
            float a[4], b[4];
            #pragma unroll
            for (int i = 0; i < 4; i++) a[i] = As[k][ty * 4 + i];
            #pragma unroll
            for (int j = 0; j < 4; j++) b[j] = Bs[k][tx * 4 + j];
            #pragma unroll
            for (int i = 0; i < 4; i++)
                #pragma unroll
                for (int j = 0; j < 4; j++) acc[i][j] += a[i] * b[j];
        }
        __syncthreads();
    }
    #pragma unroll
    for (int i = 0; i < 4; i++) {
        int row = row0 + ty * 4 + i;
        #pragma unroll
        for (int j = 0; j < 4; j++)
            C[row * HIDDEN + n0 + tx * 4 + j] = acc[i][j];
    }
}

// ---- helpers ---------------------------------------------------------------
__device__ __forceinline__ void fma2(ull& d, ull a, ull b) {
    asm("fma.rn.f32x2 %0, %1, %2, %0;" : "+l"(d) : "l"(a), "l"(b));
}
__device__ __forceinline__ ull pk(float lo, float hi) {
    ull d; asm("mov.b64 %0, {%1, %2};" : "=l"(d) : "f"(lo), "f"(hi)); return d;
}
__device__ __forceinline__ uint32_t s2u(const void* p) {
    uint32_t a;
    asm("{ .reg .u64 t; cvta.to.shared.u64 t, %1; cvt.u32.u64 %0, t; }" : "=r"(a) : "l"(p));
    return a;
}

#define MB_WAIT(mb, ph) do {                                                    \
    uint32_t _done;                                                             \
    asm volatile("{\n\t.reg .pred p;\n\t"                                       \
        "mbarrier.try_wait.parity.acquire.cluster.shared::cta.b64 p, [%1], %2;\n\t" \
        "selp.b32 %0, 1, 0, p;\n\t}"                                            \
        : "=r"(_done) : "r"(mb), "r"(ph) : "memory");                           \
    while (!_done) {                                                            \
        asm volatile("{\n\t.reg .pred p;\n\t"                                   \
            "mbarrier.try_wait.parity.acquire.cluster.shared::cta.b64 p, [%1], %2, 0x989680;\n\t" \
            "selp.b32 %0, 1, 0, p;\n\t}"                                        \
            : "=r"(_done) : "r"(mb), "r"(ph) : "memory");                       \
    }                                                                           \
} while (0)

#define MB_ARM(mb)                                                              \
    asm volatile("mbarrier.arrive.expect_tx.shared.b64 _, [%0], %1;"            \
                 :: "r"(mb), "r"(EXCH_BYTES) : "memory")

#define BULK_CLUSTER(dst, src, bytes, mb)                                       \
    asm volatile("cp.async.bulk.shared::cluster.shared::cta.mbarrier::complete_tx::bytes " \
                 "[%0], [%1], %2, [%3];"                                        \
                 :: "r"(dst), "r"(src), "r"(bytes), "r"(mb) : "memory")

// ---------------------------------------------------------------------------
// Phase 2: persistent cluster recurrence, FOUR warp-specialized engines.
//   16 clusters x 8 CTAs; rank owns 64 hidden cols (W smem-resident, shared).
//   Engine e (warps 4e..4e+3, 128 thr) runs an independent 2-batch-row chain:
//   wait(mbar_e) -> matvec -> bar_e -> reduce+update -> stage -> bar_e ->
//   8 x 512B bulk copies. Four chains interleave to hide chain latency.
//   Matvec thread tile: 2b x 8n x 32k, n-pair f32x2 (W pairs natural, h dup).
// ---------------------------------------------------------------------------
__global__ void __launch_bounds__(THREADS, 1) __cluster_dims__(CLUSTER, 1, 1)
recurrent_kernel(const float* __restrict__ Whid,
                 const float* __restrict__ noise,
                 float* __restrict__ out, int has_tail)
{
    extern __shared__ float sm[];
    const uint32_t sbase = s2u(sm);

    const int tid = threadIdx.x;
    uint32_t rank;
    asm("mov.u32 %0, %%cluster_ctarank;" : "=r"(rank));
    const int n0r   = (int)rank * 64;
    const int bbase = (blockIdx.x >> 3) * 8;

    // ---- load W slice transposed: Ws[k*64+n] = Whid[n0r+n][k] ----
    for (int i = tid; i < 64 * 128; i += THREADS) {
        int n = i >> 7, kq4 = i & 127;
        float4 v = reinterpret_cast<const float4*>(Whid)[(n0r + n) * 128 + kq4];
        sm[(4 * kq4 + 0) * 64 + n] = v.x;
        sm[(4 * kq4 + 1) * 64 + n] = v.y;
        sm[(4 * kq4 + 2) * 64 + n] = v.z;
        sm[(4 * kq4 + 3) * 64 + n] = v.w;
    }
    // ---- zero all hc buffers (h0 = 0 -> relu = 0) ----
    for (int i = tid; i < 8192; i += THREADS)
        sm[HC_OFF / 4 + i] = 0.0f;
    // ---- init + pre-arm all 8 mbarriers ----
    if (tid == 0) {
        #pragma unroll
        for (int m = 0; m < 8; m++) {
            uint32_t mb = sbase + MB_OFF + m * 8;
            asm volatile("mbarrier.init.shared.b64 [%0], %1;" :: "r"(mb), "r"(1u) : "memory");
        }
        asm volatile("fence.proxy.async.shared::cta;" ::: "memory");
        #pragma unroll
        for (int m = 0; m < 8; m++) MB_ARM(sbase + MB_OFF + m * 8);
    }
    __syncthreads();
    asm volatile("barrier.cluster.arrive.aligned;" ::: "memory");
    asm volatile("barrier.cluster.wait.aligned;"   ::: "memory");

    // ---- engine / thread mapping ----
    const int e    = tid >> 7;            // engine 0..3 (warps 4e..4e+3)
    const int etid = tid & 127;
    // matvec: kq (16 x 32k) x ng (8 x 8n); thread = 2b x 8n x 32k
    const int kq = etid >> 3;
    const int ng = etid & 7;
    const uint32_t wp0 = sbase + (uint32_t)(kq * 8192 + ng * 32);
    // scr [e][kq][b2][n64]
    const uint32_t scr_st = sbase + SCR_OFF + (uint32_t)(e * 8192 + kq * 512 + ng * 32);
    // reduce/epilogue: one output (b, col) per thread
    const int rb  = etid >> 6;            // 0..1
    const int rn  = etid & 63;            // 0..63
    const int col = n0r + rn;
    const int gb  = bbase + e * 2 + rb;
    const uint32_t scr_rd = sbase + SCR_OFF + (uint32_t)(e * 8192 + rb * 256 + rn * 4);
    const uint32_t mb0 = sbase + (uint32_t)(MB_OFF + e * 16);
    const uint32_t mb1 = mb0 + 8;
    const uint32_t hcb = sbase + (uint32_t)(HC_OFF + e * 8192);
    // peer CTA smem bases
    uint32_t peer[CLUSTER];
    #pragma unroll
    for (int r = 0; r < CLUSTER; r++)
        asm("mapa.shared::cluster.u32 %0, %1, %2;" : "=r"(peer[r]) : "r"(sbase), "r"(r));
    const uint32_t stg_base = sbase + (uint32_t)(STG_OFF + e * 1024);
    const uint32_t stg_slot = (uint32_t)((rn * 2 + rb) * 4);   // dest hc [k][b]

    float rh = 0.0f;
    int ph0 = 0, ph1 = 0;

    // prologue prefetch for s=0
    float* optr = out + ((size_t)0 * BATCH + gb) * HIDDEN + col;
    float xc  = *optr;
    float nzc = __ldg(&noise[col]);

    for (int s = 0; s < SEQ; s++) {
        const int ibuf = s & 1;
        if (s > 0) {
            uint32_t mb = ibuf ? mb1 : mb0;
            int& ph = ibuf ? ph1 : ph0;
            MB_WAIT(mb, ph);
            if (etid == 0) MB_ARM(mb);    // re-arm for step s+2
            ph ^= 1;
        }
        // prefetch NEXT step's proj + noise (a full step of latency slack)
        float xn = 0.0f, nzn = 0.0f;
        if (s + 1 < SEQ) {
            xn  = optr[BATCH * HIDDEN];
            nzn = __ldg(&noise[(size_t)(s + 1) * HIDDEN + col]);
        }

        // ---- matvec: 2b x 8n over this thread's 32-k slice ----
        const uint32_t hp0 = hcb + (uint32_t)(ibuf * 4096 + kq * 256);
        ull a00 = 0, a01 = 0, a02 = 0, a03 = 0;   // b0, n-pairs 0..3
        ull a10 = 0, a11 = 0, a12 = 0, a13 = 0;   // b1
        #pragma unroll 8
        for (int k = 0; k < 32; k++) {
            ull wp01, wp23, wp45, wp67;
            float hx, hy;
            asm("ld.shared.v2.u64 {%0,%1}, [%2];"
                : "=l"(wp01), "=l"(wp23) : "r"(wp0 + (uint32_t)(k * 256)));
            asm("ld.shared.v2.u64 {%0,%1}, [%2];"
                : "=l"(wp45), "=l"(wp67) : "r"(wp0 + (uint32_t)(k * 256 + 16)));
            asm("ld.shared.v2.f32 {%0,%1}, [%2];"
                : "=f"(hx), "=f"(hy) : "r"(hp0 + (uint32_t)(k * 8)));
            ull hd0 = pk(hx, hx), hd1 = pk(hy, hy);
            fma2(a00, hd0, wp01); fma2(a01, hd0, wp23);
            fma2(a02, hd0, wp45); fma2(a03, hd0, wp67);
            fma2(a10, hd1, wp01); fma2(a11, hd1, wp23);
            fma2(a12, hd1, wp45); fma2(a13, hd1, wp67);
        }
        // scr [kq][b][n]: (n,n+1) pairs contiguous
        asm volatile("st.shared.u64 [%0+0],   %1;" :: "r"(scr_st), "l"(a00));
        asm volatile("st.shared.u64 [%0+8],   %1;" :: "r"(scr_st), "l"(a01));
        asm volatile("st.shared.u64 [%0+16],  %1;" :: "r"(scr_st), "l"(a02));
        asm volatile("st.shared.u64 [%0+24],  %1;" :: "r"(scr_st), "l"(a03));
        asm volatile("st.shared.u64 [%0+256], %1;" :: "r"(scr_st), "l"(a10));
        asm volatile("st.shared.u64 [%0+264], %1;" :: "r"(scr_st), "l"(a11));
        asm volatile("st.shared.u64 [%0+272], %1;" :: "r"(scr_st), "l"(a12));
        asm volatile("st.shared.u64 [%0+280], %1;" :: "r"(scr_st), "l"(a13));

        // engine barrier #1: matvec partials visible
        asm volatile("bar.sync %0, 128;" :: "r"(1 + e) : "memory");

        // ---- reduce 16 k-partials + state update ----
        float acc = 0.0f;
        #pragma unroll
        for (int q = 0; q < 16; q++) {
            float v;
            asm("ld.shared.f32 %0, [%1];" : "=f"(v) : "r"(scr_rd + (uint32_t)(q * 512)));
            acc += v;
        }
        float hn = 0.5f * rh + 0.5f * (acc + xc + nzc);
        rh = hn;
        *optr = hn;

        if (s + 1 < SEQ) {
            // stage compact relu(h_new) (parity of NEXT step)
            float rv = fmaxf(hn, 0.0f);
            uint32_t stg = stg_base + (uint32_t)((ibuf ^ 1) * 512) + stg_slot;
            asm volatile("st.shared.f32 [%0], %1;" :: "r"(stg), "f"(rv) : "memory");

            // engine barrier #2: staging complete; also protects scr/hc WAR
            asm volatile("bar.sync %0, 128;" :: "r"(1 + e) : "memory");

            // ---- 8 threads issue the 8 bulk copies (512B each) ----
            if (etid < 8) {
                asm volatile("fence.proxy.async.shared::cta;" ::: "memory");
                uint32_t src    = stg_base + (uint32_t)((ibuf ^ 1) * 512);
                uint32_t dstoff = (uint32_t)(HC_OFF + e * 8192 + (ibuf ^ 1) * 4096
                                             + (int)rank * 512);
                uint32_t mboff  = (uint32_t)(MB_OFF + e * 16 + (ibuf ^ 1) * 8);
                BULK_CLUSTER(peer[etid] + dstoff, src, 512u, peer[etid] + mboff);
            }
        }
        optr += BATCH * HIDDEN;
        xc = xn; nzc = nzn;
    }

    // ---- fused tail: final hidden state ----
    if (has_tail)
        out[(size_t)SEQ * BATCH * HIDDEN + (size_t)gb * HIDDEN + col] = rh;

    // keep smem alive until all cluster peers are done
    asm volatile("barrier.cluster.arrive.aligned;" ::: "memory");
    asm volatile("barrier.cluster.wait.aligned;"   ::: "memory");
}

// ---------------------------------------------------------------------------
extern "C" void kernel_launch(void* const* d_in, const int* in_sizes, int n_in,
                              void* d_out, int out_size)
{
    const float* input = (const float*)d_in[0];
    const float* W_in  = (const float*)d_in[1];
    const float* W_hid = (const float*)d_in[2];
    const float* noise = (const float*)d_in[3];
    float* out = (float*)d_out;

    cudaFuncSetAttribute(recurrent_kernel,
                         cudaFuncAttributeMaxDynamicSharedMemorySize, SMEM_BYTES);

    dim3 grid((SEQ * BATCH) / 64, HIDDEN / 64);
    proj_kernel<<<grid, 256>>>(input, W_in, out);

    int has_tail = (out_size >= SEQ * BATCH * HIDDEN + BATCH * HIDDEN) ? 1 : 0;
    recurrent_kernel<<<128, THREADS, SMEM_BYTES>>>(W_hid, noise, out, has_tail);
}

// round 11
// speedup vs baseline: 1.7097x; 1.7097x over previous
#include <cuda_runtime.h>
#include <cstdint>

typedef unsigned long long ull;

#define SEQ    512
#define BATCH  128
#define INPUT  128
#define HIDDEN 512
#define CLUSTER 8
#define THREADS 512

// ---- recurrent smem layout (bytes) ----
// W slice  [512 k][64 n] fp32                          131072
// hc compact h: [e 2][par 2][k 512][b 4] fp32           32768 (8192 each)
// staging:  [e 2][par 2][256 vals] fp32                  4096
// scr partials: [e 2][kq 8][b 4][n 64] fp32             16384
// mbarriers: [e 2][par 2][src 8] x 8B                     256
#define HC_OFF   131072
#define STG_OFF  163840
#define SCR_OFF  167936
#define MB_OFF   184320
#define SMEM_BYTES 184576
#define EXCH_BYTES 1024u     // per (engine,parity,src) barrier: one 1KB chunk

// ---------------------------------------------------------------------------
// Phase 1: proj[row,n] = sum_k input[row,k] * W_in[n,k] -> d_out
// ---------------------------------------------------------------------------
__global__ __launch_bounds__(256) void proj_kernel(
    const float* __restrict__ A, const float* __restrict__ W,
    float* __restrict__ C)
{
    __shared__ float As[64][65];
    __shared__ float Bs[64][65];
    const int tid = threadIdx.x, tx = tid & 15, ty = tid >> 4;
    const int row0 = blockIdx.x * 64, n0 = blockIdx.y * 64;
    float acc[4][4] = {};
    for (int k0 = 0; k0 < INPUT; k0 += 64) {
        #pragma unroll
        for (int i = 0; i < 16; i++) {
            int e = tid + i * 256, r = e >> 6, kk = e & 63;
            As[kk][r] = A[(row0 + r) * INPUT + k0 + kk];
            Bs[kk][r] = W[(n0 + r) * INPUT + k0 + kk];
        }
        __syncthreads();
        #pragma unroll 8
        for (int k = 0; k < 64; k++) {
            float a[4], b[4];
            #pragma unroll
            for (int i = 0; i < 4; i++) a[i] = As[k][ty * 4 + i];
            #pragma unroll
            for (int j = 0; j < 4; j++) b[j] = Bs[k][tx * 4 + j];
            #pragma unroll
            for (int i = 0; i < 4; i++)
                #pragma unroll
                for (int j = 0; j < 4; j++) acc[i][j] += a[i] * b[j];
        }
        __syncthreads();
    }
    #pragma unroll
    for (int i = 0; i < 4; i++) {
        int row = row0 + ty * 4 + i;
        #pragma unroll
        for (int j = 0; j < 4; j++)
            C[row * HIDDEN + n0 + tx * 4 + j] = acc[i][j];
    }
}

// ---- helpers ---------------------------------------------------------------
__device__ __forceinline__ void fma2(ull& d, ull a, ull b) {
    asm("fma.rn.f32x2 %0, %1, %2, %0;" : "+l"(d) : "l"(a), "l"(b));
}
__device__ __forceinline__ ull pk(float lo, float hi) {
    ull d; asm("mov.b64 %0, {%1, %2};" : "=l"(d) : "f"(lo), "f"(hi)); return d;
}
__device__ __forceinline__ uint32_t s2u(const void* p) {
    uint32_t a;
    asm("{ .reg .u64 t; cvta.to.shared.u64 t, %1; cvt.u32.u64 %0, t; }" : "=r"(a) : "l"(p));
    return a;
}

#define MB_WAIT(mb, ph) do {                                                    \
    uint32_t _done;                                                             \
    asm volatile("{\n\t.reg .pred p;\n\t"                                       \
        "mbarrier.try_wait.parity.acquire.cluster.shared::cta.b64 p, [%1], %2;\n\t" \
        "selp.b32 %0, 1, 0, p;\n\t}"                                            \
        : "=r"(_done) : "r"(mb), "r"(ph) : "memory");                           \
    while (!_done) {                                                            \
        asm volatile("{\n\t.reg .pred p;\n\t"                                   \
            "mbarrier.try_wait.parity.acquire.cluster.shared::cta.b64 p, [%1], %2, 0x989680;\n\t" \
            "selp.b32 %0, 1, 0, p;\n\t}"                                        \
            : "=r"(_done) : "r"(mb), "r"(ph) : "memory");                       \
    }                                                                           \
} while (0)

#define MB_ARM(mb)                                                              \
    asm volatile("mbarrier.arrive.expect_tx.shared.b64 _, [%0], %1;"            \
                 :: "r"(mb), "r"(EXCH_BYTES) : "memory")

#define BULK_CLUSTER(dst, src, bytes, mb)                                       \
    asm volatile("cp.async.bulk.shared::cluster.shared::cta.mbarrier::complete_tx::bytes " \
                 "[%0], [%1], %2, [%3];"                                        \
                 :: "r"(dst), "r"(src), "r"(bytes), "r"(mb) : "memory")

// ---------------------------------------------------------------------------
// Phase 2: persistent cluster recurrence, dual engines (R8 structure) with
//   PER-SOURCE-CHUNK mbarriers. Each matvec warp's 64-k slice is exactly one
//   source rank's chunk, so each warp waits only on its own (e,par,src=kq)
//   barrier. 7/8 waits hit the fast path; only the last-arriving chunk's
//   single-warp matvec sits behind fabric delivery.
// ---------------------------------------------------------------------------
__global__ void __launch_bounds__(THREADS, 1) __cluster_dims__(CLUSTER, 1, 1)
recurrent_kernel(const float* __restrict__ Whid,
                 const float* __restrict__ noise,
                 float* __restrict__ out, int has_tail)
{
    extern __shared__ float sm[];
    const uint32_t sbase = s2u(sm);

    const int tid = threadIdx.x;
    uint32_t rank;
    asm("mov.u32 %0, %%cluster_ctarank;" : "=r"(rank));
    const int n0r   = (int)rank * 64;
    const int bbase = (blockIdx.x >> 3) * 8;

    // ---- load W slice transposed: Ws[k*64+n] = Whid[n0r+n][k] ----
    for (int e2 = tid; e2 < 64 * 128; e2 += THREADS) {
        int n = e2 >> 7, kq4 = e2 & 127;
        float4 v = reinterpret_cast<const float4*>(Whid)[(n0r + n) * 128 + kq4];
        sm[(4 * kq4 + 0) * 64 + n] = v.x;
        sm[(4 * kq4 + 1) * 64 + n] = v.y;
        sm[(4 * kq4 + 2) * 64 + n] = v.z;
        sm[(4 * kq4 + 3) * 64 + n] = v.w;
    }
    // ---- zero parity-0 compact h buffers (h0 = 0 -> relu = 0) ----
    for (int i = tid; i < 2048; i += THREADS) {
        sm[HC_OFF / 4 + i]        = 0.0f;   // engine 0, parity 0
        sm[HC_OFF / 4 + 4096 + i] = 0.0f;   // engine 1, parity 0
    }
    // ---- init + pre-arm all 32 chunk mbarriers ----
    if (tid == 0) {
        #pragma unroll
        for (int m = 0; m < 32; m++) {
            uint32_t mb = sbase + MB_OFF + m * 8;
            asm volatile("mbarrier.init.shared.b64 [%0], %1;" :: "r"(mb), "r"(1u) : "memory");
        }
        asm volatile("fence.proxy.async.shared::cta;" ::: "memory");
        #pragma unroll
        for (int m = 0; m < 32; m++) MB_ARM(sbase + MB_OFF + m * 8);
    }
    __syncthreads();
    asm volatile("barrier.cluster.arrive.aligned;" ::: "memory");
    asm volatile("barrier.cluster.wait.aligned;"   ::: "memory");

    // ---- engine / thread mapping (identical to R8) ----
    const int e    = tid >> 8;           // engine 0/1
    const int etid = tid & 255;
    // matvec: kq (8 x 64k == source rank) x bg (2 x 2b) x ng (16 x 4n)
    const int kq = etid >> 5;            // == source rank of this thread's chunk
    const int ng = etid & 15;
    const int bg = (etid >> 4) & 1;
    const uint32_t wp0 = sbase + (uint32_t)(kq * 16384 + ng * 16);
    // reduce/epilogue: one output (b, col) per thread
    const int rb   = etid >> 6;          // 0..3
    const int rn   = etid & 63;
    const int col  = n0r + rn;
    const int gb   = bbase + e * 4 + rb; // global batch row
    const uint32_t scr_st = sbase + SCR_OFF + (uint32_t)((e * 2048 + kq * 256 + 2 * bg * 64 + 4 * ng) * 4);
    const uint32_t scr_rd = sbase + SCR_OFF + (uint32_t)((e * 2048 + rb * 64 + rn) * 4);
    // this thread's chunk barriers: [e][par][src=kq]
    const uint32_t mbc0 = sbase + (uint32_t)(MB_OFF + e * 128 + 0 * 64 + kq * 8);
    const uint32_t mbc1 = sbase + (uint32_t)(MB_OFF + e * 128 + 1 * 64 + kq * 8);
    const uint32_t hcb  = sbase + (uint32_t)(HC_OFF + e * 16384);
    // peer CTA smem bases
    uint32_t peer[CLUSTER];
    #pragma unroll
    for (int r = 0; r < CLUSTER; r++)
        asm("mapa.shared::cluster.u32 %0, %1, %2;" : "=r"(peer[r]) : "r"(sbase), "r"(r));
    const uint32_t stg_base = sbase + (uint32_t)(STG_OFF + e * 2048);
    const uint32_t stg_slot = (uint32_t)((rn * 4 + rb) * 4);  // [n][b] matches dest [k][b]

    float rh = 0.0f;
    int ph0 = 0, ph1 = 0;

    for (int s = 0; s < SEQ; s++) {
        const int ibuf = s & 1;
        if (s > 0) {
            // wait ONLY for this warp's source chunk
            uint32_t mb = ibuf ? mbc1 : mbc0;
            int& ph = ibuf ? ph1 : ph0;
            MB_WAIT(mb, ph);
            if ((etid & 31) == 0) MB_ARM(mb);   // warp leader re-arms for s+2
            ph ^= 1;
        }
        // prefetch proj (in d_out) + noise for the epilogue
        float* optr = out + ((size_t)s * BATCH + gb) * HIDDEN + col;
        float x  = *optr;
        float nz = __ldg(&noise[(size_t)s * HIDDEN + col]);

        // ---- matvec over this thread's 64-k chunk (compact h, reg dup) ----
        const uint32_t hp0 = hcb + (uint32_t)(ibuf * 8192 + kq * 1024 + bg * 8);
        ull a00 = 0, a01 = 0, a10 = 0, a11 = 0;
        #pragma unroll 8
        for (int k = 0; k < 64; k++) {
            ull w01, w23;
            float hx, hy;
            asm("ld.shared.v2.u64 {%0,%1}, [%2];"
                : "=l"(w01), "=l"(w23) : "r"(wp0 + (uint32_t)(k * 256)));
            asm("ld.shared.v2.f32 {%0,%1}, [%2];"
                : "=f"(hx), "=f"(hy) : "r"(hp0 + (uint32_t)(k * 16)));
            ull h0 = pk(hx, hx), h1 = pk(hy, hy);
            fma2(a00, h0, w01); fma2(a01, h0, w23);
            fma2(a10, h1, w01); fma2(a11, h1, w23);
        }
        // partials: b=2bg at +0, b=2bg+1 at +256 bytes
        asm volatile("st.shared.v2.u64 [%0],     {%1,%2};" :: "r"(scr_st), "l"(a00), "l"(a01));
        asm volatile("st.shared.v2.u64 [%0+256], {%1,%2};" :: "r"(scr_st), "l"(a10), "l"(a11));

        // engine barrier #1: matvec partials visible
        asm volatile("bar.sync %0, 256;" :: "r"(1 + e) : "memory");

        // ---- reduce 8 k-partials + state update ----
        float acc = 0.0f;
        #pragma unroll
        for (int q = 0; q < 8; q++) {
            float v;
            asm("ld.shared.f32 %0, [%1];" : "=f"(v) : "r"(scr_rd + (uint32_t)(q * 1024)));
            acc += v;
        }
        float hn = 0.5f * rh + 0.5f * (acc + x + nz);
        rh = hn;
        *optr = hn;

        if (s < SEQ - 1) {
            // stage compact relu(h_new) locally (parity of NEXT step)
            float rv = fmaxf(hn, 0.0f);
            uint32_t stg = stg_base + (uint32_t)((ibuf ^ 1) * 1024) + stg_slot;
            asm volatile("st.shared.f32 [%0], %1;" :: "r"(stg), "f"(rv) : "memory");

            // engine barrier #2: staging complete; also protects scr/hc WAR
            asm volatile("bar.sync %0, 256;" :: "r"(1 + e) : "memory");

            // ---- 8 threads issue the 8 bulk copies (1KB each), each copy
            //      tx-counts the DESTINATION's (e, par, src=our rank) barrier
            if (etid < 8) {
                asm volatile("fence.proxy.async.shared::cta;" ::: "memory");
                uint32_t src    = stg_base + (uint32_t)((ibuf ^ 1) * 1024);
                uint32_t dstoff = (uint32_t)(HC_OFF + e * 16384 + (ibuf ^ 1) * 8192
                                             + (int)rank * 1024);
                uint32_t mboff  = (uint32_t)(MB_OFF + e * 128 + (ibuf ^ 1) * 64
                                             + (int)rank * 8);
                BULK_CLUSTER(peer[etid] + dstoff, src, 1024u, peer[etid] + mboff);
            }
        }
    }

    // ---- fused tail: final hidden state ----
    if (has_tail)
        out[(size_t)SEQ * BATCH * HIDDEN + (size_t)gb * HIDDEN + col] = rh;

    // keep smem alive until all cluster peers are done
    asm volatile("barrier.cluster.arrive.aligned;" ::: "memory");
    asm volatile("barrier.cluster.wait.aligned;"   ::: "memory");
}

// ---------------------------------------------------------------------------
extern "C" void kernel_launch(void* const* d_in, const int* in_sizes, int n_in,
                              void* d_out, int out_size)
{
    const float* input = (const float*)d_in[0];
    const float* W_in  = (const float*)d_in[1];
    const float* W_hid = (const float*)d_in[2];
    const float* noise = (const float*)d_in[3];
    float* out = (float*)d_out;

    cudaFuncSetAttribute(recurrent_kernel,
                         cudaFuncAttributeMaxDynamicSharedMemorySize, SMEM_BYTES);

    dim3 grid((SEQ * BATCH) / 64, HIDDEN / 64);
    proj_kernel<<<grid, 256>>>(input, W_in, out);

    int has_tail = (out_size >= SEQ * BATCH * HIDDEN + BATCH * HIDDEN) ? 1 : 0;
    recurrent_kernel<<<128, THREADS, SMEM_BYTES>>>(W_hid, noise, out, has_tail);
}